// round 1
// baseline (speedup 1.0000x reference)
#include <cuda_runtime.h>

#define NTOK   65536
#define DIMC   256
#define NCODE  1024
#define HWSZ   4096
#define ZSZ    16777216
#define OFF_ZQ      1
#define OFF_PERP    16777217
#define OFF_MINENC  16777218ULL
#define OFF_IDX     83886082ULL

// ---------------- scratch (device globals; no allocation) ----------------
__device__ float  g_zt[(size_t)DIMC * NTOK];   // zt[c][n]  (K-major tokens), 64 MB
__device__ float  g_et[DIMC * NCODE];          // et[c][k]  (K-major codes), 1 MB
__device__ float  g_en[NCODE];                 // |e_k|^2
__device__ float  g_zn[NTOK];                  // |z_n|^2
__device__ int    g_idx[NTOK];
__device__ int    g_hist[NCODE];
__device__ double g_loss;

// ---------------- f32x2 helpers (sm_103a FFMA2 path) ----------------
__device__ __forceinline__ unsigned long long ffma2(unsigned long long a,
                                                    unsigned long long b,
                                                    unsigned long long c) {
    unsigned long long d;
    asm("fma.rn.f32x2 %0, %1, %2, %3;" : "=l"(d) : "l"(a), "l"(b), "l"(c));
    return d;
}
__device__ __forceinline__ unsigned long long pack2(float x) {
    unsigned long long r;
    unsigned int u = __float_as_uint(x);
    asm("mov.b64 %0, {%1, %1};" : "=l"(r) : "r"(u));
    return r;
}
__device__ __forceinline__ void unpack2(unsigned long long v, float& lo, float& hi) {
    unsigned int a, b;
    asm("mov.b64 {%0, %1}, %2;" : "=r"(a), "=r"(b) : "l"(v));
    lo = __uint_as_float(a);
    hi = __uint_as_float(b);
}

// ---------------- K1: reorg z NCHW -> zt[c][n] (block copies) ----------------
__global__ void k_reorg(const float* __restrict__ z) {
    int bc = blockIdx.x;                  // bc = b*256 + c
    int b  = bc >> 8;
    int c  = bc & 255;
    const float4* src = (const float4*)(z + (size_t)bc * HWSZ);
    float4* dst = (float4*)(g_zt + (size_t)c * NTOK + (size_t)b * HWSZ);
    int t = threadIdx.x;
#pragma unroll
    for (int r = 0; r < 4; r++) dst[t + r * 256] = src[t + r * 256];
}

// ---------------- K2: |z_n|^2 ----------------
__global__ void k_znorm(const float* __restrict__ z) {
    int b   = blockIdx.x >> 4;
    int hw  = ((blockIdx.x & 15) << 8) + threadIdx.x;
    const float* p = z + (size_t)b * DIMC * HWSZ + hw;
    float s = 0.0f;
#pragma unroll 8
    for (int c = 0; c < DIMC; c++) {
        float v = p[(size_t)c * HWSZ];
        s = fmaf(v, v, s);
    }
    g_zn[b * HWSZ + hw] = s;
}

// ---------------- K3: embed transpose + |e_k|^2 + zero accumulators ----------------
__global__ void k_prep(const float* __restrict__ e) {
    int k = blockIdx.x;
    int t = threadIdx.x;                  // 64 threads, 4 floats each
    float4 v = ((const float4*)(e + (size_t)k * DIMC))[t];
    int c = t * 4;
    g_et[(c + 0) * NCODE + k] = v.x;
    g_et[(c + 1) * NCODE + k] = v.y;
    g_et[(c + 2) * NCODE + k] = v.z;
    g_et[(c + 3) * NCODE + k] = v.w;
    float s = v.x * v.x + v.y * v.y + v.z * v.z + v.w * v.w;
#pragma unroll
    for (int o = 16; o; o >>= 1) s += __shfl_down_sync(0xffffffffu, s, o);
    __shared__ float sh[2];
    if ((t & 31) == 0) sh[t >> 5] = s;
    __syncthreads();
    if (t == 0) {
        g_en[k]   = sh[0] + sh[1];
        g_hist[k] = 0;
        if (k == 0) g_loss = 0.0;
    }
}

// ---------------- K4: zero min_encodings region ----------------
__global__ void k_zero(float* __restrict__ out) {
    float2* p = (float2*)(out + OFF_MINENC);
    size_t i = (size_t)blockIdx.x * 256 + threadIdx.x;   // 33,554,432 float2
    p[i] = make_float2(0.0f, 0.0f);
}

// ---------------- K5: fused distance GEMM + argmin (fp32 exact, FFMA2) ----------------
// 64 tokens per block, all 1024 codes scanned. threads 256: tx=code group, ty=token group.
__global__ void __launch_bounds__(256) k_argmin() {
    __shared__ float As[64 * 64];    // As[k_local][t] 16 KB
    __shared__ float Bs[64 * 128];   // Bs[k_local][c] 32 KB
    int tid = threadIdx.x;
    int tx  = tid & 15;              // 16 code groups  (8 codes each)
    int ty  = tid >> 4;              // 16 token groups (4 tokens each)
    int n0  = blockIdx.x * 64;

    float zn[4], bv[4];
    int bi[4];
#pragma unroll
    for (int i = 0; i < 4; i++) {
        zn[i] = g_zn[n0 + ty * 4 + i];
        bv[i] = 3.4e38f;
        bi[i] = 0;
    }

    for (int ct = 0; ct < 8; ct++) {                 // 8 code tiles of 128
        unsigned long long acc[4][4];                // [code-pair][token]
#pragma unroll
        for (int p = 0; p < 4; p++)
#pragma unroll
            for (int i = 0; i < 4; i++) acc[p][i] = 0ULL;

        for (int kk = 0; kk < 256; kk += 64) {
            __syncthreads();
            // load As[64][64]: 1024 float4, 4 per thread (coalesced)
#pragma unroll
            for (int r = 0; r < 4; r++) {
                int q = tid + r * 256;
                int k = q >> 4, c4 = q & 15;
                *(float4*)(As + k * 64 + c4 * 4) =
                    *(const float4*)(g_zt + (size_t)(kk + k) * NTOK + n0 + c4 * 4);
            }
            // load Bs[64][128]: 2048 float4, 8 per thread (coalesced)
#pragma unroll
            for (int r = 0; r < 8; r++) {
                int q = tid + r * 256;
                int k = q >> 5, c4 = q & 31;
                *(float4*)(Bs + k * 128 + c4 * 4) =
                    *(const float4*)(g_et + (size_t)(kk + k) * NCODE + ct * 128 + c4 * 4);
            }
            __syncthreads();
#pragma unroll 4
            for (int k = 0; k < 64; k++) {
                float4 a = *(const float4*)(As + k * 64 + ty * 4);
                ulonglong2 b01 = *(const ulonglong2*)(Bs + k * 128 + tx * 8);
                ulonglong2 b23 = *(const ulonglong2*)(Bs + k * 128 + tx * 8 + 4);
                unsigned long long a0 = pack2(a.x), a1 = pack2(a.y);
                unsigned long long a2 = pack2(a.z), a3 = pack2(a.w);
                acc[0][0] = ffma2(b01.x, a0, acc[0][0]);
                acc[0][1] = ffma2(b01.x, a1, acc[0][1]);
                acc[0][2] = ffma2(b01.x, a2, acc[0][2]);
                acc[0][3] = ffma2(b01.x, a3, acc[0][3]);
                acc[1][0] = ffma2(b01.y, a0, acc[1][0]);
                acc[1][1] = ffma2(b01.y, a1, acc[1][1]);
                acc[1][2] = ffma2(b01.y, a2, acc[1][2]);
                acc[1][3] = ffma2(b01.y, a3, acc[1][3]);
                acc[2][0] = ffma2(b23.x, a0, acc[2][0]);
                acc[2][1] = ffma2(b23.x, a1, acc[2][1]);
                acc[2][2] = ffma2(b23.x, a2, acc[2][2]);
                acc[2][3] = ffma2(b23.x, a3, acc[2][3]);
                acc[3][0] = ffma2(b23.y, a0, acc[3][0]);
                acc[3][1] = ffma2(b23.y, a1, acc[3][1]);
                acc[3][2] = ffma2(b23.y, a2, acc[3][2]);
                acc[3][3] = ffma2(b23.y, a3, acc[3][3]);
            }
        }
        // epilogue: d = (zn + en) - 2*dot, track min (ascending code order)
#pragma unroll
        for (int p = 0; p < 4; p++) {
            int c0 = ct * 128 + tx * 8 + p * 2;
            float e0 = g_en[c0], e1 = g_en[c0 + 1];
#pragma unroll
            for (int i = 0; i < 4; i++) {
                float d0, d1;
                unpack2(acc[p][i], d0, d1);
                float v0 = (zn[i] + e0) - 2.0f * d0;
                float v1 = (zn[i] + e1) - 2.0f * d1;
                if (v0 < bv[i]) { bv[i] = v0; bi[i] = c0; }
                if (v1 < bv[i]) { bv[i] = v1; bi[i] = c0 + 1; }
            }
        }
    }

    // reduce across the 16 tx lanes per token (first-index tie-break)
#pragma unroll
    for (int i = 0; i < 4; i++) {
        float v = bv[i];
        int ix = bi[i];
#pragma unroll
        for (int o = 8; o; o >>= 1) {
            float ov = __shfl_xor_sync(0xffffffffu, v, o);
            int   oi = __shfl_xor_sync(0xffffffffu, ix, o);
            if (ov < v || (ov == v && oi < ix)) { v = ov; ix = oi; }
        }
        if (tx == 0) g_idx[n0 + ty * 4 + i] = ix;
    }
}

// ---------------- K6: z_q gather (NCHW, straight-through rounding) + loss ----------------
__global__ void k_epi(const float* __restrict__ z, float* __restrict__ out) {
    size_t i = (size_t)blockIdx.x * 256 + threadIdx.x;   // linear over [b][c][hw]
    int hw = (int)(i & 4095);
    int c  = (int)((i >> 12) & 255);
    int b  = (int)(i >> 20);
    int k  = g_idx[b * HWSZ + hw];
    float zv = z[i];
    float q  = __ldg(&g_et[(size_t)c * NCODE + k]);
    float d  = q - zv;                 // matches sg(z_q - zp) rounding
    out[OFF_ZQ + i] = zv + d;          // straight-through value
    float s = d * d;
#pragma unroll
    for (int o = 16; o; o >>= 1) s += __shfl_down_sync(0xffffffffu, s, o);
    __shared__ float red[8];
    int t = threadIdx.x;
    if ((t & 31) == 0) red[t >> 5] = s;
    __syncthreads();
    if (t < 8) {
        float w = red[t];
#pragma unroll
        for (int o = 4; o; o >>= 1) w += __shfl_down_sync(0x000000ffu, w, o);
        if (t == 0) atomicAdd(&g_loss, (double)w);
    }
}

// ---------------- K7: one-hot scatter + idx + histogram ----------------
__global__ void k_scat(float* __restrict__ out) {
    int n = blockIdx.x * 256 + threadIdx.x;
    int k = g_idx[n];
    out[OFF_MINENC + (size_t)n * NCODE + k] = 1.0f;
    out[OFF_IDX + n] = (float)k;
    atomicAdd(&g_hist[k], 1);
}

// ---------------- K8: loss + perplexity finalize ----------------
__global__ void k_fin(float* __restrict__ out) {
    int t = threadIdx.x;  // 1024
    float em = (float)g_hist[t] * (1.0f / 65536.0f);
    float v = em * logf(em + 1e-10f);
    __shared__ float sh[32];
#pragma unroll
    for (int o = 16; o; o >>= 1) v += __shfl_down_sync(0xffffffffu, v, o);
    if ((t & 31) == 0) sh[t >> 5] = v;
    __syncthreads();
    if (t < 32) {
        float w = sh[t];
#pragma unroll
        for (int o = 16; o; o >>= 1) w += __shfl_down_sync(0xffffffffu, w, o);
        if (t == 0) {
            out[OFF_PERP] = expf(-w);
            out[0] = (float)(g_loss * (1.25 / 16777216.0));
        }
    }
}

// ---------------- launch ----------------
extern "C" void kernel_launch(void* const* d_in, const int* in_sizes, int n_in,
                              void* d_out, int out_size) {
    const float* z = (const float*)d_in[0];
    const float* e = (const float*)d_in[1];
    float* out = (float*)d_out;
    (void)in_sizes; (void)n_in; (void)out_size;

    k_prep  <<<NCODE, 64>>>(e);
    k_reorg <<<4096, 256>>>(z);
    k_znorm <<<256, 256>>>(z);
    k_zero  <<<131072, 256>>>(out);
    k_argmin<<<NTOK / 64, 256>>>();
    k_epi   <<<ZSZ / 256, 256>>>(z, out);
    k_scat  <<<NTOK / 256, 256>>>(out);
    k_fin   <<<1, 1024>>>(out);
}